// round 2
// baseline (speedup 1.0000x reference)
#include <cuda_runtime.h>
#include <cuda_bf16.h>
#include <cstdint>

#define NN 100000
#define EE 1600000
#define F1 128
#define F2 64

// Scratch (static device globals: allocation-free rule)
__device__ __align__(16) float g_agg1[NN * F1];
__device__ __align__(16) float g_cnt[NN];
__device__ __align__(16) float g_h[NN * F1];
__device__ __align__(16) float g_hl[NN * F2];
__device__ __align__(16) float g_agg2[NN * F2];

__device__ __forceinline__ void red_add_v4(float* p, float4 v) {
    asm volatile("red.global.add.v4.f32 [%0], {%1,%2,%3,%4};"
                 :: "l"(p), "f"(v.x), "f"(v.y), "f"(v.z), "f"(v.w)
                 : "memory");
}

// ---------------------------------------------------------------------------
// Zero scratch accumulators (must run every launch: graph replays)
// ---------------------------------------------------------------------------
__global__ void zero_kernel() {
    int tid = blockIdx.x * blockDim.x + threadIdx.x;
    int stride = gridDim.x * blockDim.x;
    float4 z = make_float4(0.f, 0.f, 0.f, 0.f);
    float4* a1 = (float4*)g_agg1;   // 3,200,000 float4
    float4* a2 = (float4*)g_agg2;   // 1,600,000 float4
    float4* c  = (float4*)g_cnt;    //    25,000 float4
    for (int i = tid; i < NN * F1 / 4; i += stride) a1[i] = z;
    for (int i = tid; i < NN * F2 / 4; i += stride) a2[i] = z;
    for (int i = tid; i < NN / 4;      i += stride) c[i]  = z;
}

// ---------------------------------------------------------------------------
// Layer-1 edge scatter: agg1[dst] += x[src] (128 f32 per edge, 1 warp/edge)
// plus degree count. edge_index is int32 (JAX x64 disabled demotes int64).
// ---------------------------------------------------------------------------
__global__ void scatter1_kernel(const float* __restrict__ x,
                                const int* __restrict__ ei) {
    int gw   = (blockIdx.x * blockDim.x + threadIdx.x) >> 5;
    int lane = threadIdx.x & 31;
    int nw   = (gridDim.x * blockDim.x) >> 5;
    for (int e = gw; e < EE; e += nw) {
        int s = ei[e];
        int d = ei[EE + e];
        float4 v = ((const float4*)(x + (size_t)s * F1))[lane];
        red_add_v4(g_agg1 + (size_t)d * F1 + lane * 4, v);
        if (lane == 0) atomicAdd(g_cnt + d, 1.0f);
    }
}

// ---------------------------------------------------------------------------
// Layer-2 edge scatter: agg2[dst] += hl[src] (64 f32 per edge, half-warp/edge)
// ---------------------------------------------------------------------------
__global__ void scatter2_kernel(const int* __restrict__ ei) {
    int tid = blockIdx.x * blockDim.x + threadIdx.x;
    int hw  = tid >> 4;
    int l   = tid & 15;
    int nhw = (gridDim.x * blockDim.x) >> 4;
    for (int e = hw; e < EE; e += nhw) {
        int s = ei[e];
        int d = ei[EE + e];
        float4 v = ((const float4*)(g_hl + (size_t)s * F2))[l];
        red_add_v4(g_agg2 + (size_t)d * F2 + l * 4, v);
    }
}

// ---------------------------------------------------------------------------
// Layer 1: h = relu(BN(mean @ W1l^T + b1l + x @ W1r^T))
// Weights transposed in SMEM; each warp does 4 nodes, each lane 4 channels.
// ---------------------------------------------------------------------------
__global__ void layer1_kernel(const float* __restrict__ x,
                              const float* __restrict__ W1l,
                              const float* __restrict__ b1l,
                              const float* __restrict__ W1r,
                              const float* __restrict__ gamma,
                              const float* __restrict__ beta,
                              const float* __restrict__ rmean,
                              const float* __restrict__ rvar) {
    extern __shared__ float sm[];
    float* WTl = sm;            // [128][128] : WTl[k*128+j] = W1l[j][k]
    float* WTr = sm + 16384;    // [128][128]
    float* buf = sm + 32768;    // per warp: [4 nodes][x row 128 | mean row 128]

    for (int i = threadIdx.x; i < 16384; i += blockDim.x) {
        int k = i >> 7, j = i & 127;
        WTl[i] = W1l[j * 128 + k];
        WTr[i] = W1r[j * 128 + k];
    }
    __syncthreads();

    int wid = threadIdx.x >> 5, lane = threadIdx.x & 31;
    float* xb = buf + wid * 1024;   // [4][128]
    float* mb = xb + 512;           // [4][128]

    // fold BN params for this lane's 4 channels (c = 4*lane .. 4*lane+3)
    float4 g4  = ((const float4*)gamma)[lane];
    float4 be4 = ((const float4*)beta)[lane];
    float4 rm4 = ((const float4*)rmean)[lane];
    float4 rv4 = ((const float4*)rvar)[lane];
    float4 bl4 = ((const float4*)b1l)[lane];
    float4 scale, shift;
    scale.x = g4.x * rsqrtf(rv4.x + 1e-5f);
    scale.y = g4.y * rsqrtf(rv4.y + 1e-5f);
    scale.z = g4.z * rsqrtf(rv4.z + 1e-5f);
    scale.w = g4.w * rsqrtf(rv4.w + 1e-5f);
    shift.x = (bl4.x - rm4.x) * scale.x + be4.x;
    shift.y = (bl4.y - rm4.y) * scale.y + be4.y;
    shift.z = (bl4.z - rm4.z) * scale.z + be4.z;
    shift.w = (bl4.w - rm4.w) * scale.w + be4.w;

    int gw = blockIdx.x * (blockDim.x >> 5) + wid;
    int nw = gridDim.x * (blockDim.x >> 5);
    const int NTASK = NN / 4;   // 25000

    for (int t = gw; t < NTASK; t += nw) {
        int base = t * 4;
        #pragma unroll
        for (int m = 0; m < 4; m++) {
            int node = base + m;
            ((float4*)(xb + m * 128))[lane] =
                ((const float4*)(x + (size_t)node * F1))[lane];
            float inv = 1.0f / fmaxf(g_cnt[node], 1.0f);
            float4 a = ((const float4*)(g_agg1 + (size_t)node * F1))[lane];
            a.x *= inv; a.y *= inv; a.z *= inv; a.w *= inv;
            ((float4*)(mb + m * 128))[lane] = a;
        }
        __syncwarp();

        float4 accl[4], accr[4];
        #pragma unroll
        for (int m = 0; m < 4; m++) {
            accl[m] = make_float4(0.f, 0.f, 0.f, 0.f);
            accr[m] = make_float4(0.f, 0.f, 0.f, 0.f);
        }
        #pragma unroll 4
        for (int k = 0; k < 128; k++) {
            float4 wl = ((float4*)(WTl + k * 128))[lane];
            float4 wr = ((float4*)(WTr + k * 128))[lane];
            #pragma unroll
            for (int m = 0; m < 4; m++) {
                float mv = mb[m * 128 + k];
                float xv = xb[m * 128 + k];
                accl[m].x = fmaf(mv, wl.x, accl[m].x);
                accl[m].y = fmaf(mv, wl.y, accl[m].y);
                accl[m].z = fmaf(mv, wl.z, accl[m].z);
                accl[m].w = fmaf(mv, wl.w, accl[m].w);
                accr[m].x = fmaf(xv, wr.x, accr[m].x);
                accr[m].y = fmaf(xv, wr.y, accr[m].y);
                accr[m].z = fmaf(xv, wr.z, accr[m].z);
                accr[m].w = fmaf(xv, wr.w, accr[m].w);
            }
        }
        #pragma unroll
        for (int m = 0; m < 4; m++) {
            float4 o;
            o.x = fmaxf((accl[m].x + accr[m].x) * scale.x + shift.x, 0.f);
            o.y = fmaxf((accl[m].y + accr[m].y) * scale.y + shift.y, 0.f);
            o.z = fmaxf((accl[m].z + accr[m].z) * scale.z + shift.z, 0.f);
            o.w = fmaxf((accl[m].w + accr[m].w) * scale.w + shift.w, 0.f);
            ((float4*)(g_h + (size_t)(base + m) * F1))[lane] = o;
        }
        __syncwarp();
    }
}

// ---------------------------------------------------------------------------
// hl = h @ W2l^T   (projection BEFORE aggregation: halves layer-2 edge traffic)
// ---------------------------------------------------------------------------
__global__ void hl_kernel(const float* __restrict__ W2l) {
    extern __shared__ float sm[];
    float* WT  = sm;          // [128][64] : WT[k*64+j] = W2l[j][k]
    float* buf = sm + 8192;   // per warp: [4][128]

    for (int i = threadIdx.x; i < 8192; i += blockDim.x) {
        int k = i >> 6, j = i & 63;
        WT[i] = W2l[j * 128 + k];
    }
    __syncthreads();

    int wid = threadIdx.x >> 5, lane = threadIdx.x & 31;
    float* hb = buf + wid * 512;
    int gw = blockIdx.x * (blockDim.x >> 5) + wid;
    int nw = gridDim.x * (blockDim.x >> 5);
    const int NTASK = NN / 4;

    for (int t = gw; t < NTASK; t += nw) {
        int base = t * 4;
        #pragma unroll
        for (int m = 0; m < 4; m++)
            ((float4*)(hb + m * 128))[lane] =
                ((const float4*)(g_h + (size_t)(base + m) * F1))[lane];
        __syncwarp();

        float2 acc[4];
        #pragma unroll
        for (int m = 0; m < 4; m++) acc[m] = make_float2(0.f, 0.f);
        #pragma unroll 4
        for (int k = 0; k < 128; k++) {
            float2 w = ((float2*)(WT + k * 64))[lane];
            #pragma unroll
            for (int m = 0; m < 4; m++) {
                float hv = hb[m * 128 + k];
                acc[m].x = fmaf(hv, w.x, acc[m].x);
                acc[m].y = fmaf(hv, w.y, acc[m].y);
            }
        }
        #pragma unroll
        for (int m = 0; m < 4; m++)
            ((float2*)(g_hl + (size_t)(base + m) * F2))[lane] = acc[m];
        __syncwarp();
    }
}

// ---------------------------------------------------------------------------
// out = agg2/cnt + b2l + h @ W2r^T
// ---------------------------------------------------------------------------
__global__ void out_kernel(const float* __restrict__ W2r,
                           const float* __restrict__ b2l,
                           float* __restrict__ out) {
    extern __shared__ float sm[];
    float* WT  = sm;          // [128][64]
    float* buf = sm + 8192;

    for (int i = threadIdx.x; i < 8192; i += blockDim.x) {
        int k = i >> 6, j = i & 63;
        WT[i] = W2r[j * 128 + k];
    }
    __syncthreads();

    int wid = threadIdx.x >> 5, lane = threadIdx.x & 31;
    float* hb = buf + wid * 512;
    float2 b2 = ((const float2*)b2l)[lane];
    int gw = blockIdx.x * (blockDim.x >> 5) + wid;
    int nw = gridDim.x * (blockDim.x >> 5);
    const int NTASK = NN / 4;

    for (int t = gw; t < NTASK; t += nw) {
        int base = t * 4;
        #pragma unroll
        for (int m = 0; m < 4; m++)
            ((float4*)(hb + m * 128))[lane] =
                ((const float4*)(g_h + (size_t)(base + m) * F1))[lane];
        __syncwarp();

        float2 acc[4];
        #pragma unroll
        for (int m = 0; m < 4; m++) acc[m] = make_float2(0.f, 0.f);
        #pragma unroll 4
        for (int k = 0; k < 128; k++) {
            float2 w = ((float2*)(WT + k * 64))[lane];
            #pragma unroll
            for (int m = 0; m < 4; m++) {
                float hv = hb[m * 128 + k];
                acc[m].x = fmaf(hv, w.x, acc[m].x);
                acc[m].y = fmaf(hv, w.y, acc[m].y);
            }
        }
        #pragma unroll
        for (int m = 0; m < 4; m++) {
            int node = base + m;
            float inv = 1.0f / fmaxf(g_cnt[node], 1.0f);
            float2 a2 = ((float2*)(g_agg2 + (size_t)node * F2))[lane];
            float2 o;
            o.x = acc[m].x + a2.x * inv + b2.x;
            o.y = acc[m].y + a2.y * inv + b2.y;
            ((float2*)(out + (size_t)node * F2))[lane] = o;
        }
        __syncwarp();
    }
}

// ---------------------------------------------------------------------------
extern "C" void kernel_launch(void* const* d_in, const int* in_sizes, int n_in,
                              void* d_out, int out_size) {
    const float* x     = (const float*)d_in[0];
    const int*   ei    = (const int*)d_in[1];
    const float* W1l   = (const float*)d_in[2];
    const float* b1l   = (const float*)d_in[3];
    const float* W1r   = (const float*)d_in[4];
    const float* gamma = (const float*)d_in[5];
    const float* beta  = (const float*)d_in[6];
    const float* rmean = (const float*)d_in[7];
    const float* rvar  = (const float*)d_in[8];
    const float* W2l   = (const float*)d_in[9];
    const float* b2l   = (const float*)d_in[10];
    const float* W2r   = (const float*)d_in[11];
    float* out = (float*)d_out;

    const int SMEM1 = (16384 + 16384 + 16 * 1024) * 4;  // 192 KB
    const int SMEM2 = (8192 + 16 * 512) * 4;            // 64 KB
    cudaFuncSetAttribute(layer1_kernel, cudaFuncAttributeMaxDynamicSharedMemorySize, SMEM1);
    cudaFuncSetAttribute(hl_kernel,     cudaFuncAttributeMaxDynamicSharedMemorySize, SMEM2);
    cudaFuncSetAttribute(out_kernel,    cudaFuncAttributeMaxDynamicSharedMemorySize, SMEM2);

    zero_kernel<<<1024, 256>>>();
    scatter1_kernel<<<8192, 256>>>(x, ei);
    layer1_kernel<<<148, 512, SMEM1>>>(x, W1l, b1l, W1r, gamma, beta, rmean, rvar);
    hl_kernel<<<444, 512, SMEM2>>>(W2l);
    scatter2_kernel<<<8192, 256>>>(ei);
    out_kernel<<<444, 512, SMEM2>>>(W2r, b2l, out);
}